// round 9
// baseline (speedup 1.0000x reference)
#include <cuda_runtime.h>
#include <cuda_bf16.h>
#include <cstdint>

// ============================================================================
// RGNN via warp-level mma.sync, bf16x3 split precision (sm_100-safe path).
//   h_t = relu( sum_k L^{k+1} (x_t W_k + h_{t-1} H_k) ), B=8,T=16,N=1024,F=128,K=4
//
// R8: 3-stage ring (61KB -> 3 CTAs/SM, 12 warps), cp.async issued before the
// MMA burst, register double-buffered fragments, term-major MMA ordering.
//
//   MODE 2 (powers):  Lslot[s] = Lslot[s-1] @ L^T-major     K=1024, grid 16x16
//   MODE 1 (feature): St[(k,g)][(b,m)] = WHT @ [x_t|h]      K=256,  grid 128x8
//   MODE 0 (main):    z[m][(b,g)] = Lcat @ St^T             K=4096, grid 16x16
// ============================================================================

// ---------------- device globals ----------------
__device__ __align__(256) __nv_bfloat16 g_Lh  [1024u * 4096u]; // L^1..L^4 hi [m][k]
__device__ __align__(256) __nv_bfloat16 g_Ll  [1024u * 4096u]; // lo
__device__ __align__(256) __nv_bfloat16 g_LTh [1024u * 1024u]; // L^T hi [n][k]
__device__ __align__(256) __nv_bfloat16 g_LTl [1024u * 1024u];
__device__ __align__(256) __nv_bfloat16 g_Sth [1024u * 4096u]; // St hi [(b,g)][(k,m)]
__device__ __align__(256) __nv_bfloat16 g_Stl [1024u * 4096u];
__device__ __align__(256) __nv_bfloat16 g_xh  [16777216u];     // x hi [b][t][n][f]
__device__ __align__(256) __nv_bfloat16 g_xl  [16777216u];
__device__ __align__(256) __nv_bfloat16 g_hh  [1048576u];      // h hi [(b*1024+n)][f]
__device__ __align__(256) __nv_bfloat16 g_hl  [1048576u];
__device__ __align__(256) __nv_bfloat16 g_WHTh[512u * 256u];   // WHT hi [(k*128+g)][f']
__device__ __align__(256) __nv_bfloat16 g_WHTl[512u * 256u];

// ---------------- helpers ----------------
__device__ __forceinline__ uint32_t smem_u32(const void* p) {
    uint32_t a;
    asm("{ .reg .u64 t; cvta.to.shared.u64 t, %1; cvt.u32.u64 %0, t; }"
        : "=r"(a) : "l"(p));
    return a;
}
__device__ __forceinline__ void cp16(uint32_t dst, const void* src) {
    asm volatile("cp.async.cg.shared.global [%0], [%1], 16;" :: "r"(dst), "l"(src));
}
__device__ __forceinline__ void ldm4(uint32_t* r, uint32_t a) {
    asm volatile("ldmatrix.sync.aligned.m8n8.x4.shared.b16 {%0,%1,%2,%3}, [%4];"
        : "=r"(r[0]), "=r"(r[1]), "=r"(r[2]), "=r"(r[3]) : "r"(a));
}
__device__ __forceinline__ void mma16816(float* d, const uint32_t* a, const uint32_t* b) {
    asm volatile(
        "mma.sync.aligned.m16n8k16.row.col.f32.bf16.bf16.f32 "
        "{%0,%1,%2,%3}, {%4,%5,%6,%7}, {%8,%9}, {%0,%1,%2,%3};"
        : "+f"(d[0]), "+f"(d[1]), "+f"(d[2]), "+f"(d[3])
        : "r"(a[0]), "r"(a[1]), "r"(a[2]), "r"(a[3]), "r"(b[0]), "r"(b[1]));
}
__device__ __forceinline__ void split2(float v, __nv_bfloat16& h, __nv_bfloat16& l) {
    h = __float2bfloat16(v);
    l = __float2bfloat16(v - __bfloat162float(h));
}

// ---------------- smem geometry ----------------
// 32 bf16 per row = 64B data + 16B pad -> pitch 80B (conflict-free ldmatrix rows)
static constexpr int PITCH    = 80;
static constexpr int TILE_B   = 64 * PITCH;       // 5120 (64 rows x 32 bf16)
static constexpr int STAGE_B  = 4 * TILE_B;       // Ah, Al, Bh, Bl = 20480
static constexpr int STAGES   = 3;
static constexpr int SMEM_TOT = STAGES * STAGE_B; // 61440 -> 3 CTAs/SM

// ============================================================================
// Unified GEMM kernel. CTA tile 64(m) x 64(n), 4 warps of 32x32, k-chunk 32.
// 3-stage cp.async ring, prefetch distance 2, loads issued before MMA burst,
// register double-buffered fragments, term-major MMA order.
// All modes: 3-term bf16 split (AhBh + AhBl + AlBh).
// ============================================================================
template<int MODE>
__global__ __launch_bounds__(128, 3)
void mma_k(float* __restrict__ out, const int targ)   // targ = t (0,1) or slot (2)
{
    extern __shared__ __align__(128) char sm[];
    const uint32_t smb = smem_u32(sm);
    const int tid  = threadIdx.x;
    const int wid  = tid >> 5, lane = tid & 31;
    const int row0 = blockIdx.y * 64;
    const int n0   = blockIdx.x * 64;

    constexpr int NCH = (MODE == 0) ? 128 : (MODE == 1 ? 8 : 32);

    const __nv_bfloat16 *Ah, *Al;
    int lda;
    if (MODE == 1) {
        Ah = g_WHTh + (size_t)row0 * 256; Al = g_WHTl + (size_t)row0 * 256; lda = 256;
    } else {
        const int kofs = (MODE == 2) ? (targ - 1) * 1024 : 0;
        Ah = g_Lh + (size_t)row0 * 4096 + kofs;
        Al = g_Ll + (size_t)row0 * 4096 + kofs;
        lda = 4096;
    }

    auto load_chunk = [&](int stage, int ch) {
        const int k0 = ch * 32;
        const uint32_t base = smb + stage * STAGE_B;
        // A: 64 rows x 32 bf16, hi+lo
#pragma unroll
        for (int i = 0; i < 2; ++i) {
            const int idx = i * 128 + tid;          // 0..255
            const int r = idx >> 2, c16 = idx & 3;
            const size_t o = (size_t)r * lda + k0 + c16 * 8;
            const uint32_t d = base + r * PITCH + c16 * 16;
            cp16(d,          Ah + o);
            cp16(d + TILE_B, Al + o);
        }
        // B: 64 rows x 32 bf16, hi+lo
#pragma unroll
        for (int i = 0; i < 2; ++i) {
            const int idx = i * 128 + tid;
            const int r = idx >> 2, c16 = idx & 3;
            const __nv_bfloat16 *sh, *sl;
            if (MODE == 0) {
                const size_t o = (size_t)(n0 + r) * 4096 + k0 + c16 * 8;
                sh = g_Sth + o; sl = g_Stl + o;
            } else if (MODE == 2) {
                const size_t o = (size_t)(n0 + r) * 1024 + k0 + c16 * 8;
                sh = g_LTh + o; sl = g_LTl + o;
            } else {
                const int j = n0 + r, b = j >> 10, m = j & 1023;
                if (k0 < 128) {
                    const size_t o = (((size_t)(b * 16 + targ)) * 1024 + m) * 128
                                   + k0 + c16 * 8;
                    sh = g_xh + o; sl = g_xl + o;
                } else {
                    const size_t o = ((size_t)(b * 1024 + m)) * 128
                                   + (k0 - 128) + c16 * 8;
                    sh = g_hh + o; sl = g_hl + o;
                }
            }
            const uint32_t d = base + 2 * TILE_B + r * PITCH + c16 * 16;
            cp16(d,          sh);
            cp16(d + TILE_B, sl);
        }
        asm volatile("cp.async.commit_group;" ::: "memory");
    };

    const int warp_m = (wid & 1) * 32;
    const int warp_n = (wid >> 1) * 32;

    float acc[2][4][4];
#pragma unroll
    for (int a = 0; a < 2; ++a)
#pragma unroll
        for (int b = 0; b < 4; ++b)
#pragma unroll
            for (int c = 0; c < 4; ++c) acc[a][b][c] = 0.f;

    // double-buffered fragments (buffer = kk & 1)
    uint32_t ah[2][2][4], al[2][2][4], bh[2][2][4], bl[2][2][4];

    // fragment loader for sub-step kk (kc = kk*16) from given stage base
    auto ldf = [&](int b, int kc, uint32_t Ab, uint32_t Bb) {
#pragma unroll
        for (int mi = 0; mi < 2; ++mi) {
            const int r = warp_m + mi * 16 + (lane & 7) + ((lane >> 3) & 1) * 8;
            const int c = kc + (lane >> 4) * 8;
            const uint32_t ad = Ab + r * PITCH + c * 2;
            ldm4(ah[b][mi], ad);
            ldm4(al[b][mi], ad + TILE_B);
        }
#pragma unroll
        for (int gi = 0; gi < 2; ++gi) {
            const int r = warp_n + gi * 16 + ((lane >> 4) & 1) * 8 + (lane & 7);
            const int c = kc + ((lane >> 3) & 1) * 8;
            const uint32_t bd = Bb + r * PITCH + c * 2;
            ldm4(bh[b][gi], bd);
            ldm4(bl[b][gi], bd + TILE_B);
        }
    };

    // prefetch 2 chunks (NCH >= 8 in all modes)
    load_chunk(0, 0);
    load_chunk(1, 1);

#pragma unroll 1
    for (int ch = 0; ch < NCH; ++ch) {
        if (ch + 1 < NCH)
            asm volatile("cp.async.wait_group 1;" ::: "memory");
        else
            asm volatile("cp.async.wait_group 0;" ::: "memory");
        __syncthreads();
        // Writing stage (ch+2)%3 == stage read at chunk ch-1; the barrier above
        // guarantees all warps finished chunk ch-1 -> WAR-safe.
        if (ch + 2 < NCH)
            load_chunk((ch + 2) % 3, ch + 2);

        const int stage = ch % 3;
        const uint32_t Ab = smb + stage * STAGE_B;
        const uint32_t Bb = Ab + 2 * TILE_B;

        ldf(0, 0, Ab, Bb);
#pragma unroll
        for (int kk = 0; kk < 2; ++kk) {
            if (kk == 0) ldf(1, 16, Ab, Bb);   // hide LDSM latency under MMAs
            const int b = kk;
            // term-major order: 8 independent accs between same-acc updates;
            // per-acc order (hh, hl, lh) identical to prior rounds.
#pragma unroll
            for (int mi = 0; mi < 2; ++mi)
#pragma unroll
                for (int ni = 0; ni < 4; ++ni)
                    mma16816(acc[mi][ni], ah[b][mi], &bh[b][ni >> 1][(ni & 1) * 2]);
#pragma unroll
            for (int mi = 0; mi < 2; ++mi)
#pragma unroll
                for (int ni = 0; ni < 4; ++ni)
                    mma16816(acc[mi][ni], ah[b][mi], &bl[b][ni >> 1][(ni & 1) * 2]);
#pragma unroll
            for (int mi = 0; mi < 2; ++mi)
#pragma unroll
                for (int ni = 0; ni < 4; ++ni)
                    mma16816(acc[mi][ni], al[b][mi], &bh[b][ni >> 1][(ni & 1) * 2]);
        }
    }

    // ---------------- epilogue ----------------
#pragma unroll
    for (int mi = 0; mi < 2; ++mi)
#pragma unroll
        for (int ni = 0; ni < 4; ++ni)
#pragma unroll
            for (int half = 0; half < 2; ++half) {
                const int gm = row0 + warp_m + mi * 16 + (lane >> 2) + half * 8;
                const int gn = n0 + warp_n + ni * 8 + 2 * (lane & 3);
                float v0 = acc[mi][ni][half * 2 + 0];
                float v1 = acc[mi][ni][half * 2 + 1];
                if (MODE == 0) {
                    v0 = fmaxf(v0, 0.f); v1 = fmaxf(v1, 0.f);
                    const int b = gn >> 7, g = gn & 127;
                    *(float2*)(out + (((size_t)(b * 16 + targ)) * 1024 + gm) * 128 + g)
                        = make_float2(v0, v1);
                    __nv_bfloat16 h0, l0, h1, l1;
                    split2(v0, h0, l0); split2(v1, h1, l1);
                    const size_t ho = ((size_t)(b * 1024 + gm)) * 128 + g;
                    *(__nv_bfloat162*)(g_hh + ho) = __halves2bfloat162(h0, h1);
                    *(__nv_bfloat162*)(g_hl + ho) = __halves2bfloat162(l0, l1);
                } else if (MODE == 1) {
                    const int kk = gm >> 7, g = gm & 127;
                    const int b = gn >> 10, m = gn & 1023;
                    __nv_bfloat16 h0, l0, h1, l1;
                    split2(v0, h0, l0); split2(v1, h1, l1);
                    const size_t o = ((size_t)(b * 128 + g)) * 4096 + kk * 1024 + m;
                    *(__nv_bfloat162*)(g_Sth + o) = __halves2bfloat162(h0, h1);
                    *(__nv_bfloat162*)(g_Stl + o) = __halves2bfloat162(l0, l1);
                } else {
                    __nv_bfloat16 h0, l0, h1, l1;
                    split2(v0, h0, l0); split2(v1, h1, l1);
                    const size_t o = (size_t)gm * 4096 + targ * 1024 + gn;
                    *(__nv_bfloat162*)(g_Lh + o) = __halves2bfloat162(h0, h1);
                    *(__nv_bfloat162*)(g_Ll + o) = __halves2bfloat162(l0, l1);
                }
            }
}

// ---------------- prep kernels ----------------
__global__ void splitL0_k(const float* __restrict__ L)
{
    const int e = blockIdx.x * 256 + threadIdx.x;       // 1M
    const int r = e >> 10, c = e & 1023;
    __nv_bfloat16 h, l;
    split2(L[e], h, l);
    g_Lh[(size_t)r * 4096 + c] = h;
    g_Ll[(size_t)r * 4096 + c] = l;
}

__global__ void transLT_k(const float* __restrict__ L)
{
    __shared__ float tile[32][33];
    const int bx = blockIdx.x * 32, by = blockIdx.y * 32;
    const int x = threadIdx.x, y = threadIdx.y;          // block (32, 8)
#pragma unroll
    for (int i = 0; i < 32; i += 8)
        tile[y + i][x] = L[(size_t)(by + y + i) * 1024 + bx + x];
    __syncthreads();
#pragma unroll
    for (int i = 0; i < 32; i += 8) {
        __nv_bfloat16 h, l;
        split2(tile[x][y + i], h, l);                    // = L[by+x][bx+y+i]
        const size_t o = (size_t)(bx + y + i) * 1024 + by + x;
        g_LTh[o] = h;
        g_LTl[o] = l;
    }
}

__global__ void splitX_k(const float* __restrict__ x)
{
    const size_t e = ((size_t)blockIdx.x * 256 + threadIdx.x) * 4;
    const float4 v = *(const float4*)(x + e);
    __nv_bfloat16 h0, l0, h1, l1, h2, l2, h3, l3;
    split2(v.x, h0, l0); split2(v.y, h1, l1);
    split2(v.z, h2, l2); split2(v.w, h3, l3);
    *(__nv_bfloat162*)(g_xh + e)     = __halves2bfloat162(h0, h1);
    *(__nv_bfloat162*)(g_xh + e + 2) = __halves2bfloat162(h2, h3);
    *(__nv_bfloat162*)(g_xl + e)     = __halves2bfloat162(l0, l1);
    *(__nv_bfloat162*)(g_xl + e + 2) = __halves2bfloat162(l2, l3);
}

__global__ void catWHT_k(const float* __restrict__ W, const float* __restrict__ H)
{
    const int e = blockIdx.x * 256 + threadIdx.x;        // 512*256
    const int kg = e >> 8, f = e & 255;
    const int k = kg >> 7, g = kg & 127;
    const float v = (f < 128) ? W[k * 16384 + f * 128 + g]
                              : H[k * 16384 + (f - 128) * 128 + g];
    __nv_bfloat16 hi, lo;
    split2(v, hi, lo);
    g_WHTh[e] = hi;
    g_WHTl[e] = lo;
}

__global__ void zeroH_k()
{
    const size_t e = ((size_t)blockIdx.x * 256 + threadIdx.x) * 4;
    *(uint2*)(g_hh + e) = make_uint2(0u, 0u);
    *(uint2*)(g_hl + e) = make_uint2(0u, 0u);
}

// ---------------- launch ----------------
extern "C" void kernel_launch(void* const* d_in, const int* in_sizes, int n_in,
                              void* d_out, int out_size)
{
    const float* x = (const float*)d_in[0]; // [8,16,1024,128]
    const float* L = (const float*)d_in[1]; // [1024,1024]
    const float* W = (const float*)d_in[2]; // [4,128,128]
    const float* H = (const float*)d_in[3]; // [4,128,128]
    float* out = (float*)d_out;
    (void)in_sizes; (void)n_in; (void)out_size;

    cudaFuncSetAttribute(mma_k<0>, cudaFuncAttributeMaxDynamicSharedMemorySize, SMEM_TOT);
    cudaFuncSetAttribute(mma_k<1>, cudaFuncAttributeMaxDynamicSharedMemorySize, SMEM_TOT);
    cudaFuncSetAttribute(mma_k<2>, cudaFuncAttributeMaxDynamicSharedMemorySize, SMEM_TOT);

    // Order keeps an MMA kernel at profiled-launch index 3 (power GEMM).
    splitL0_k<<<4096, 256>>>(L);                           // 0
    transLT_k<<<dim3(32, 32), dim3(32, 8)>>>(L);           // 1
    for (int s = 1; s < 4; ++s)                            // 2,3,4
        mma_k<2><<<dim3(16, 16), 128, SMEM_TOT>>>(nullptr, s);
    catWHT_k <<<512, 256>>>(W, H);                         // 5
    splitX_k <<<16384, 256>>>(x);                          // 6
    zeroH_k  <<<1024, 256>>>();                            // 7

    for (int t = 0; t < 16; ++t) {
        mma_k<1><<<dim3(128, 8), 128, SMEM_TOT>>>(nullptr, t); // St = WHT @ [x_t|h]
        mma_k<0><<<dim3(16, 16), 128, SMEM_TOT>>>(out, t);     // z = Lcat @ St^T
    }
}

// round 10
// speedup vs baseline: 1.0768x; 1.0768x over previous
#include <cuda_runtime.h>
#include <cuda_bf16.h>
#include <cstdint>

// ============================================================================
// RGNN via warp-level mma.sync, bf16x3 split precision (sm_100-safe path).
//   h_t = relu( sum_k L^{k+1} (x_t W_k + h_{t-1} H_k) ), B=8,T=16,N=1024,F=128,K=4
//
// R9: split-K=4 on the 1024x1024-output GEMMs (grid 256 -> 1024 CTAs; achieved
// occupancy was grid-capped at ~1.7 CTA/SM). fp32 partials + reduce kernels.
// Inner loop identical to R7 (fastest verified variant).
//
//   MODE 2 (powers):  Cpart[z] = Lslot[s-1] @ L^T (K=256/z), reduce->split slot s
//   MODE 1 (feature): St[(k,g)][(b,m)] = WHT @ [x_t|h]      K=256, grid 128x8
//   MODE 0 (main):    Cpart[z] = Lcat @ St^T (K=1024/z), reduce->relu->out,h
// ============================================================================

// ---------------- device globals ----------------
__device__ __align__(256) __nv_bfloat16 g_Lh  [1024u * 4096u]; // L^1..L^4 hi [m][k]
__device__ __align__(256) __nv_bfloat16 g_Ll  [1024u * 4096u]; // lo
__device__ __align__(256) __nv_bfloat16 g_LTh [1024u * 1024u]; // L^T hi [n][k]
__device__ __align__(256) __nv_bfloat16 g_LTl [1024u * 1024u];
__device__ __align__(256) __nv_bfloat16 g_Sth [1024u * 4096u]; // St hi [(b,g)][(k,m)]
__device__ __align__(256) __nv_bfloat16 g_Stl [1024u * 4096u];
__device__ __align__(256) __nv_bfloat16 g_xh  [16777216u];     // x hi [b][t][n][f]
__device__ __align__(256) __nv_bfloat16 g_xl  [16777216u];
__device__ __align__(256) __nv_bfloat16 g_hh  [1048576u];      // h hi [(b*1024+n)][f]
__device__ __align__(256) __nv_bfloat16 g_hl  [1048576u];
__device__ __align__(256) __nv_bfloat16 g_WHTh[512u * 256u];   // WHT hi [(k*128+g)][f']
__device__ __align__(256) __nv_bfloat16 g_WHTl[512u * 256u];
__device__ __align__(256) float         g_Cpart[4u * 1024u * 1024u]; // split-K partials

// ---------------- helpers ----------------
__device__ __forceinline__ uint32_t smem_u32(const void* p) {
    uint32_t a;
    asm("{ .reg .u64 t; cvta.to.shared.u64 t, %1; cvt.u32.u64 %0, t; }"
        : "=r"(a) : "l"(p));
    return a;
}
__device__ __forceinline__ void cp16(uint32_t dst, const void* src) {
    asm volatile("cp.async.cg.shared.global [%0], [%1], 16;" :: "r"(dst), "l"(src));
}
__device__ __forceinline__ void ldm4(uint32_t* r, uint32_t a) {
    asm volatile("ldmatrix.sync.aligned.m8n8.x4.shared.b16 {%0,%1,%2,%3}, [%4];"
        : "=r"(r[0]), "=r"(r[1]), "=r"(r[2]), "=r"(r[3]) : "r"(a));
}
__device__ __forceinline__ void mma16816(float* d, const uint32_t* a, const uint32_t* b) {
    asm volatile(
        "mma.sync.aligned.m16n8k16.row.col.f32.bf16.bf16.f32 "
        "{%0,%1,%2,%3}, {%4,%5,%6,%7}, {%8,%9}, {%0,%1,%2,%3};"
        : "+f"(d[0]), "+f"(d[1]), "+f"(d[2]), "+f"(d[3])
        : "r"(a[0]), "r"(a[1]), "r"(a[2]), "r"(a[3]), "r"(b[0]), "r"(b[1]));
}
__device__ __forceinline__ void split2(float v, __nv_bfloat16& h, __nv_bfloat16& l) {
    h = __float2bfloat16(v);
    l = __float2bfloat16(v - __bfloat162float(h));
}

// ---------------- smem geometry ----------------
static constexpr int PITCH    = 80;
static constexpr int TILE_B   = 64 * PITCH;       // 5120 (64 rows x 32 bf16)
static constexpr int STAGE_B  = 4 * TILE_B;       // Ah, Al, Bh, Bl = 20480
static constexpr int STAGES   = 4;
static constexpr int SMEM_TOT = STAGES * STAGE_B; // 81920

// ============================================================================
// Unified GEMM kernel. CTA tile 64(m) x 64(n), 4 warps of 32x32, k-chunk 32.
// 4-stage cp.async ring, prefetch distance 3 (R7 structure).
// MODE 0: main  split-K=4 (K=1024/CTA) -> Cpart
// MODE 1: feature (K=256)              -> St splits
// MODE 2: powers split-K=4 (K=256/CTA) -> Cpart
// ============================================================================
template<int MODE>
__global__ __launch_bounds__(128, 2)
void mma_k(float* __restrict__ out, const int targ)   // targ = t (0,1) or slot (2)
{
    extern __shared__ __align__(128) char sm[];
    const uint32_t smb = smem_u32(sm);
    const int tid  = threadIdx.x;
    const int wid  = tid >> 5, lane = tid & 31;
    const int row0 = blockIdx.y * 64;
    const int n0   = blockIdx.x * 64;

    constexpr int NCH = (MODE == 0) ? 32 : 8;     // k-chunks of 32 per CTA
    const int kbase = (MODE == 1) ? 0 : blockIdx.z * (NCH * 32);

    const __nv_bfloat16 *Ah, *Al;
    int lda;
    if (MODE == 1) {
        Ah = g_WHTh + (size_t)row0 * 256; Al = g_WHTl + (size_t)row0 * 256; lda = 256;
    } else {
        const int kofs = (MODE == 2) ? (targ - 1) * 1024 : 0;
        Ah = g_Lh + (size_t)row0 * 4096 + kofs;
        Al = g_Ll + (size_t)row0 * 4096 + kofs;
        lda = 4096;
    }

    auto load_chunk = [&](int stage, int ch) {
        const int k0 = kbase + ch * 32;
        const uint32_t base = smb + stage * STAGE_B;
        // A: 64 rows x 32 bf16, hi+lo
#pragma unroll
        for (int i = 0; i < 2; ++i) {
            const int idx = i * 128 + tid;          // 0..255
            const int r = idx >> 2, c16 = idx & 3;
            const size_t o = (size_t)r * lda + k0 + c16 * 8;
            const uint32_t d = base + r * PITCH + c16 * 16;
            cp16(d,          Ah + o);
            cp16(d + TILE_B, Al + o);
        }
        // B: 64 rows x 32 bf16, hi+lo
#pragma unroll
        for (int i = 0; i < 2; ++i) {
            const int idx = i * 128 + tid;
            const int r = idx >> 2, c16 = idx & 3;
            const __nv_bfloat16 *sh, *sl;
            if (MODE == 0) {
                const size_t o = (size_t)(n0 + r) * 4096 + k0 + c16 * 8;
                sh = g_Sth + o; sl = g_Stl + o;
            } else if (MODE == 2) {
                const size_t o = (size_t)(n0 + r) * 1024 + k0 + c16 * 8;
                sh = g_LTh + o; sl = g_LTl + o;
            } else {
                const int j = n0 + r, b = j >> 10, m = j & 1023;
                if (k0 < 128) {
                    const size_t o = (((size_t)(b * 16 + targ)) * 1024 + m) * 128
                                   + k0 + c16 * 8;
                    sh = g_xh + o; sl = g_xl + o;
                } else {
                    const size_t o = ((size_t)(b * 1024 + m)) * 128
                                   + (k0 - 128) + c16 * 8;
                    sh = g_hh + o; sl = g_hl + o;
                }
            }
            const uint32_t d = base + 2 * TILE_B + r * PITCH + c16 * 16;
            cp16(d,          sh);
            cp16(d + TILE_B, sl);
        }
        asm volatile("cp.async.commit_group;" ::: "memory");
    };

    const int warp_m = (wid & 1) * 32;
    const int warp_n = (wid >> 1) * 32;

    float acc[2][4][4];
#pragma unroll
    for (int a = 0; a < 2; ++a)
#pragma unroll
        for (int b = 0; b < 4; ++b)
#pragma unroll
            for (int c = 0; c < 4; ++c) acc[a][b][c] = 0.f;

    // prefetch 3 chunks (NCH >= 8 in all modes)
    load_chunk(0, 0);
    load_chunk(1, 1);
    load_chunk(2, 2);

#pragma unroll 1
    for (int ch = 0; ch < NCH; ++ch) {
        if (ch + 3 <= NCH)
            asm volatile("cp.async.wait_group 2;" ::: "memory");
        else if (ch + 2 == NCH)
            asm volatile("cp.async.wait_group 1;" ::: "memory");
        else
            asm volatile("cp.async.wait_group 0;" ::: "memory");
        __syncthreads();

        const int stage = ch & 3;
        const uint32_t Ab = smb + stage * STAGE_B;
        const uint32_t Bb = Ab + 2 * TILE_B;
#pragma unroll
        for (int kk = 0; kk < 2; ++kk) {
            const int kc = kk * 16;
            uint32_t ah[2][4], al[2][4], bh[2][4], bl[2][4];
#pragma unroll
            for (int mi = 0; mi < 2; ++mi) {
                const int r = warp_m + mi * 16 + (lane & 7) + ((lane >> 3) & 1) * 8;
                const int c = kc + (lane >> 4) * 8;
                const uint32_t ad = Ab + r * PITCH + c * 2;
                ldm4(ah[mi], ad);
                ldm4(al[mi], ad + TILE_B);
            }
#pragma unroll
            for (int gi = 0; gi < 2; ++gi) {
                const int r = warp_n + gi * 16 + ((lane >> 4) & 1) * 8 + (lane & 7);
                const int c = kc + ((lane >> 3) & 1) * 8;
                const uint32_t bd = Bb + r * PITCH + c * 2;
                ldm4(bh[gi], bd);
                ldm4(bl[gi], bd + TILE_B);
            }
#pragma unroll
            for (int mi = 0; mi < 2; ++mi)
#pragma unroll
                for (int ni = 0; ni < 4; ++ni) {
                    const uint32_t* bhp = &bh[ni >> 1][(ni & 1) * 2];
                    const uint32_t* blp = &bl[ni >> 1][(ni & 1) * 2];
                    mma16816(acc[mi][ni], ah[mi], bhp);
                    mma16816(acc[mi][ni], ah[mi], blp);
                    mma16816(acc[mi][ni], al[mi], bhp);
                }
        }
        if (ch + 3 < NCH)
            load_chunk((ch + 3) & 3, ch + 3);
    }

    // ---------------- epilogue ----------------
#pragma unroll
    for (int mi = 0; mi < 2; ++mi)
#pragma unroll
        for (int ni = 0; ni < 4; ++ni)
#pragma unroll
            for (int half = 0; half < 2; ++half) {
                const int gm = row0 + warp_m + mi * 16 + (lane >> 2) + half * 8;
                const int gn = n0 + warp_n + ni * 8 + 2 * (lane & 3);
                float v0 = acc[mi][ni][half * 2 + 0];
                float v1 = acc[mi][ni][half * 2 + 1];
                if (MODE == 1) {
                    const int kk = gm >> 7, g = gm & 127;
                    const int b = gn >> 10, m = gn & 1023;
                    __nv_bfloat16 h0, l0, h1, l1;
                    split2(v0, h0, l0); split2(v1, h1, l1);
                    const size_t o = ((size_t)(b * 128 + g)) * 4096 + kk * 1024 + m;
                    *(__nv_bfloat162*)(g_Sth + o) = __halves2bfloat162(h0, h1);
                    *(__nv_bfloat162*)(g_Stl + o) = __halves2bfloat162(l0, l1);
                } else {
                    // split-K partial (fp32)
                    *(float2*)(g_Cpart + (size_t)blockIdx.z * 1048576u
                                       + (size_t)gm * 1024 + gn)
                        = make_float2(v0, v1);
                }
            }
}

// ---------------- reduce kernels ----------------
__global__ void reduce_pow_k(int slot)
{
    const size_t e = ((size_t)blockIdx.x * 256 + threadIdx.x) * 4;
    const float4 a = *(const float4*)(g_Cpart + e);
    const float4 b = *(const float4*)(g_Cpart + 1048576u + e);
    const float4 c = *(const float4*)(g_Cpart + 2097152u + e);
    const float4 d = *(const float4*)(g_Cpart + 3145728u + e);
    const float4 s = make_float4(a.x + b.x + c.x + d.x, a.y + b.y + c.y + d.y,
                                 a.z + b.z + c.z + d.z, a.w + b.w + c.w + d.w);
    const int m = (int)(e >> 10), n = (int)(e & 1023);
    __nv_bfloat16 h0, l0, h1, l1, h2, l2, h3, l3;
    split2(s.x, h0, l0); split2(s.y, h1, l1);
    split2(s.z, h2, l2); split2(s.w, h3, l3);
    const size_t o = (size_t)m * 4096 + (size_t)slot * 1024 + n;
    *(__nv_bfloat162*)(g_Lh + o)     = __halves2bfloat162(h0, h1);
    *(__nv_bfloat162*)(g_Lh + o + 2) = __halves2bfloat162(h2, h3);
    *(__nv_bfloat162*)(g_Ll + o)     = __halves2bfloat162(l0, l1);
    *(__nv_bfloat162*)(g_Ll + o + 2) = __halves2bfloat162(l2, l3);
}

__global__ void reduce_relu_k(float* __restrict__ out, int t)
{
    const size_t e = ((size_t)blockIdx.x * 256 + threadIdx.x) * 4;
    const float4 a = *(const float4*)(g_Cpart + e);
    const float4 b = *(const float4*)(g_Cpart + 1048576u + e);
    const float4 c = *(const float4*)(g_Cpart + 2097152u + e);
    const float4 d = *(const float4*)(g_Cpart + 3145728u + e);
    float4 s = make_float4(a.x + b.x + c.x + d.x, a.y + b.y + c.y + d.y,
                           a.z + b.z + c.z + d.z, a.w + b.w + c.w + d.w);
    s.x = fmaxf(s.x, 0.f); s.y = fmaxf(s.y, 0.f);
    s.z = fmaxf(s.z, 0.f); s.w = fmaxf(s.w, 0.f);
    const int m = (int)(e >> 10);
    const int j = (int)(e & 1023);
    const int b8 = j >> 7, g = j & 127;
    *(float4*)(out + (((size_t)(b8 * 16 + t)) * 1024 + m) * 128 + g) = s;
    __nv_bfloat16 h0, l0, h1, l1, h2, l2, h3, l3;
    split2(s.x, h0, l0); split2(s.y, h1, l1);
    split2(s.z, h2, l2); split2(s.w, h3, l3);
    const size_t ho = ((size_t)(b8 * 1024 + m)) * 128 + g;
    *(__nv_bfloat162*)(g_hh + ho)     = __halves2bfloat162(h0, h1);
    *(__nv_bfloat162*)(g_hh + ho + 2) = __halves2bfloat162(h2, h3);
    *(__nv_bfloat162*)(g_hl + ho)     = __halves2bfloat162(l0, l1);
    *(__nv_bfloat162*)(g_hl + ho + 2) = __halves2bfloat162(l2, l3);
}

// ---------------- prep kernels ----------------
__global__ void splitL0_k(const float* __restrict__ L)
{
    const int e = blockIdx.x * 256 + threadIdx.x;       // 1M
    const int r = e >> 10, c = e & 1023;
    __nv_bfloat16 h, l;
    split2(L[e], h, l);
    g_Lh[(size_t)r * 4096 + c] = h;
    g_Ll[(size_t)r * 4096 + c] = l;
}

__global__ void transLT_k(const float* __restrict__ L)
{
    __shared__ float tile[32][33];
    const int bx = blockIdx.x * 32, by = blockIdx.y * 32;
    const int x = threadIdx.x, y = threadIdx.y;          // block (32, 8)
#pragma unroll
    for (int i = 0; i < 32; i += 8)
        tile[y + i][x] = L[(size_t)(by + y + i) * 1024 + bx + x];
    __syncthreads();
#pragma unroll
    for (int i = 0; i < 32; i += 8) {
        __nv_bfloat16 h, l;
        split2(tile[x][y + i], h, l);                    // = L[by+x][bx+y+i]
        const size_t o = (size_t)(bx + y + i) * 1024 + by + x;
        g_LTh[o] = h;
        g_LTl[o] = l;
    }
}

__global__ void splitX_k(const float* __restrict__ x)
{
    const size_t e = ((size_t)blockIdx.x * 256 + threadIdx.x) * 4;
    const float4 v = *(const float4*)(x + e);
    __nv_bfloat16 h0, l0, h1, l1, h2, l2, h3, l3;
    split2(v.x, h0, l0); split2(v.y, h1, l1);
    split2(v.z, h2, l2); split2(v.w, h3, l3);
    *(__nv_bfloat162*)(g_xh + e)     = __halves2bfloat162(h0, h1);
    *(__nv_bfloat162*)(g_xh + e + 2) = __halves2bfloat162(h2, h3);
    *(__nv_bfloat162*)(g_xl + e)     = __halves2bfloat162(l0, l1);
    *(__nv_bfloat162*)(g_xl + e + 2) = __halves2bfloat162(l2, l3);
}

__global__ void catWHT_k(const float* __restrict__ W, const float* __restrict__ H)
{
    const int e = blockIdx.x * 256 + threadIdx.x;        // 512*256
    const int kg = e >> 8, f = e & 255;
    const int k = kg >> 7, g = kg & 127;
    const float v = (f < 128) ? W[k * 16384 + f * 128 + g]
                              : H[k * 16384 + (f - 128) * 128 + g];
    __nv_bfloat16 hi, lo;
    split2(v, hi, lo);
    g_WHTh[e] = hi;
    g_WHTl[e] = lo;
}

__global__ void zeroH_k()
{
    const size_t e = ((size_t)blockIdx.x * 256 + threadIdx.x) * 4;
    *(uint2*)(g_hh + e) = make_uint2(0u, 0u);
    *(uint2*)(g_hl + e) = make_uint2(0u, 0u);
}

// ---------------- launch ----------------
extern "C" void kernel_launch(void* const* d_in, const int* in_sizes, int n_in,
                              void* d_out, int out_size)
{
    const float* x = (const float*)d_in[0]; // [8,16,1024,128]
    const float* L = (const float*)d_in[1]; // [1024,1024]
    const float* W = (const float*)d_in[2]; // [4,128,128]
    const float* H = (const float*)d_in[3]; // [4,128,128]
    float* out = (float*)d_out;
    (void)in_sizes; (void)n_in; (void)out_size;

    cudaFuncSetAttribute(mma_k<0>, cudaFuncAttributeMaxDynamicSharedMemorySize, SMEM_TOT);
    cudaFuncSetAttribute(mma_k<1>, cudaFuncAttributeMaxDynamicSharedMemorySize, SMEM_TOT);
    cudaFuncSetAttribute(mma_k<2>, cudaFuncAttributeMaxDynamicSharedMemorySize, SMEM_TOT);

    splitL0_k<<<4096, 256>>>(L);                           // 0
    transLT_k<<<dim3(32, 32), dim3(32, 8)>>>(L);           // 1
    catWHT_k <<<512, 256>>>(W, H);                         // 2
    splitX_k <<<16384, 256>>>(x);                          // 3
    zeroH_k  <<<1024, 256>>>();                            // 4

    // L powers: split-K=4 + reduce/split
    for (int s = 1; s < 4; ++s) {                          // 5..10
        mma_k<2><<<dim3(16, 16, 4), 128, SMEM_TOT>>>(nullptr, s);
        reduce_pow_k<<<1024, 256>>>(s);
    }

    for (int t = 0; t < 16; ++t) {
        mma_k<1><<<dim3(128, 8), 128, SMEM_TOT>>>(nullptr, t);       // St
        mma_k<0><<<dim3(16, 16, 4), 128, SMEM_TOT>>>(nullptr, t);    // Cpart
        reduce_relu_k<<<1024, 256>>>(out, t);                        // out, h
    }
}

// round 11
// speedup vs baseline: 1.2282x; 1.1406x over previous
#include <cuda_runtime.h>
#include <cuda_bf16.h>
#include <cstdint>

// ============================================================================
// RGNN via warp-level mma.sync, bf16x3 split precision (sm_100-safe path).
//   h_t = relu( sum_k L^{k+1} (x_t W_k + h_{t-1} H_k) ), B=8,T=16,N=1024,F=128,K=4
//
// R10: 3-stage ring (61KB -> 3 CTAs/SM = 12 warps) + R7 inner loop (verified
// fastest) + main split-K=8 (2048 CTAs, 4.6 waves vs 2.3 -> less tail waste).
//
//   MODE 2 (powers):  Cpart[z] = Lslot[s-1] @ L^T (K=256/z,z<4) -> reduce/split
//   MODE 1 (feature): St[(k,g)][(b,m)] = WHT @ [x_t|h]  K=256, grid 128x8
//   MODE 0 (main):    Cpart[z] = Lcat @ St^T (K=512/z,z<8) -> reduce/relu
// ============================================================================

// ---------------- device globals ----------------
__device__ __align__(256) __nv_bfloat16 g_Lh  [1024u * 4096u]; // L^1..L^4 hi [m][k]
__device__ __align__(256) __nv_bfloat16 g_Ll  [1024u * 4096u]; // lo
__device__ __align__(256) __nv_bfloat16 g_LTh [1024u * 1024u]; // L^T hi [n][k]
__device__ __align__(256) __nv_bfloat16 g_LTl [1024u * 1024u];
__device__ __align__(256) __nv_bfloat16 g_Sth [1024u * 4096u]; // St hi [(b,g)][(k,m)]
__device__ __align__(256) __nv_bfloat16 g_Stl [1024u * 4096u];
__device__ __align__(256) __nv_bfloat16 g_xh  [16777216u];     // x hi [b][t][n][f]
__device__ __align__(256) __nv_bfloat16 g_xl  [16777216u];
__device__ __align__(256) __nv_bfloat16 g_hh  [1048576u];      // h hi [(b*1024+n)][f]
__device__ __align__(256) __nv_bfloat16 g_hl  [1048576u];
__device__ __align__(256) __nv_bfloat16 g_WHTh[512u * 256u];   // WHT hi [(k*128+g)][f']
__device__ __align__(256) __nv_bfloat16 g_WHTl[512u * 256u];
__device__ __align__(256) float         g_Cpart[8u * 1024u * 1024u]; // split-K partials

// ---------------- helpers ----------------
__device__ __forceinline__ uint32_t smem_u32(const void* p) {
    uint32_t a;
    asm("{ .reg .u64 t; cvta.to.shared.u64 t, %1; cvt.u32.u64 %0, t; }"
        : "=r"(a) : "l"(p));
    return a;
}
__device__ __forceinline__ void cp16(uint32_t dst, const void* src) {
    asm volatile("cp.async.cg.shared.global [%0], [%1], 16;" :: "r"(dst), "l"(src));
}
__device__ __forceinline__ void ldm4(uint32_t* r, uint32_t a) {
    asm volatile("ldmatrix.sync.aligned.m8n8.x4.shared.b16 {%0,%1,%2,%3}, [%4];"
        : "=r"(r[0]), "=r"(r[1]), "=r"(r[2]), "=r"(r[3]) : "r"(a));
}
__device__ __forceinline__ void mma16816(float* d, const uint32_t* a, const uint32_t* b) {
    asm volatile(
        "mma.sync.aligned.m16n8k16.row.col.f32.bf16.bf16.f32 "
        "{%0,%1,%2,%3}, {%4,%5,%6,%7}, {%8,%9}, {%0,%1,%2,%3};"
        : "+f"(d[0]), "+f"(d[1]), "+f"(d[2]), "+f"(d[3])
        : "r"(a[0]), "r"(a[1]), "r"(a[2]), "r"(a[3]), "r"(b[0]), "r"(b[1]));
}
__device__ __forceinline__ void split2(float v, __nv_bfloat16& h, __nv_bfloat16& l) {
    h = __float2bfloat16(v);
    l = __float2bfloat16(v - __bfloat162float(h));
}

// ---------------- smem geometry ----------------
static constexpr int PITCH    = 80;
static constexpr int TILE_B   = 64 * PITCH;       // 5120 (64 rows x 32 bf16)
static constexpr int STAGE_B  = 4 * TILE_B;       // Ah, Al, Bh, Bl = 20480
static constexpr int STAGES   = 3;
static constexpr int SMEM_TOT = STAGES * STAGE_B; // 61440 -> 3 CTAs/SM

// ============================================================================
// Unified GEMM kernel. CTA tile 64(m) x 64(n), 4 warps of 32x32, k-chunk 32.
// 3-stage cp.async ring, prefetch distance 2, R7 chunk structure
// (wait -> barrier -> LDSM+MMA burst -> issue next load).
// MODE 0: main  split-K=8 (K=512/CTA)  -> Cpart
// MODE 1: feature (K=256)              -> St splits
// MODE 2: powers split-K=4 (K=256/CTA) -> Cpart
// ============================================================================
template<int MODE>
__global__ __launch_bounds__(128, 3)
void mma_k(float* __restrict__ out, const int targ)   // targ = t (0,1) or slot (2)
{
    extern __shared__ __align__(128) char sm[];
    const uint32_t smb = smem_u32(sm);
    const int tid  = threadIdx.x;
    const int wid  = tid >> 5, lane = tid & 31;
    const int row0 = blockIdx.y * 64;
    const int n0   = blockIdx.x * 64;

    constexpr int NCH = (MODE == 0) ? 16 : 8;     // k-chunks of 32 per CTA
    const int kbase = (MODE == 1) ? 0 : blockIdx.z * (NCH * 32);

    const __nv_bfloat16 *Ah, *Al;
    int lda;
    if (MODE == 1) {
        Ah = g_WHTh + (size_t)row0 * 256; Al = g_WHTl + (size_t)row0 * 256; lda = 256;
    } else {
        const int kofs = (MODE == 2) ? (targ - 1) * 1024 : 0;
        Ah = g_Lh + (size_t)row0 * 4096 + kofs;
        Al = g_Ll + (size_t)row0 * 4096 + kofs;
        lda = 4096;
    }

    auto load_chunk = [&](int stage, int ch) {
        const int k0 = kbase + ch * 32;
        const uint32_t base = smb + stage * STAGE_B;
        // A: 64 rows x 32 bf16, hi+lo
#pragma unroll
        for (int i = 0; i < 2; ++i) {
            const int idx = i * 128 + tid;          // 0..255
            const int r = idx >> 2, c16 = idx & 3;
            const size_t o = (size_t)r * lda + k0 + c16 * 8;
            const uint32_t d = base + r * PITCH + c16 * 16;
            cp16(d,          Ah + o);
            cp16(d + TILE_B, Al + o);
        }
        // B: 64 rows x 32 bf16, hi+lo
#pragma unroll
        for (int i = 0; i < 2; ++i) {
            const int idx = i * 128 + tid;
            const int r = idx >> 2, c16 = idx & 3;
            const __nv_bfloat16 *sh, *sl;
            if (MODE == 0) {
                const size_t o = (size_t)(n0 + r) * 4096 + k0 + c16 * 8;
                sh = g_Sth + o; sl = g_Stl + o;
            } else if (MODE == 2) {
                const size_t o = (size_t)(n0 + r) * 1024 + k0 + c16 * 8;
                sh = g_LTh + o; sl = g_LTl + o;
            } else {
                const int j = n0 + r, b = j >> 10, m = j & 1023;
                if (k0 < 128) {
                    const size_t o = (((size_t)(b * 16 + targ)) * 1024 + m) * 128
                                   + k0 + c16 * 8;
                    sh = g_xh + o; sl = g_xl + o;
                } else {
                    const size_t o = ((size_t)(b * 1024 + m)) * 128
                                   + (k0 - 128) + c16 * 8;
                    sh = g_hh + o; sl = g_hl + o;
                }
            }
            const uint32_t d = base + 2 * TILE_B + r * PITCH + c16 * 16;
            cp16(d,          sh);
            cp16(d + TILE_B, sl);
        }
        asm volatile("cp.async.commit_group;" ::: "memory");
    };

    const int warp_m = (wid & 1) * 32;
    const int warp_n = (wid >> 1) * 32;

    float acc[2][4][4];
#pragma unroll
    for (int a = 0; a < 2; ++a)
#pragma unroll
        for (int b = 0; b < 4; ++b)
#pragma unroll
            for (int c = 0; c < 4; ++c) acc[a][b][c] = 0.f;

    // prefetch 2 chunks (NCH >= 8 in all modes)
    load_chunk(0, 0);
    load_chunk(1, 1);

#pragma unroll 1
    for (int ch = 0; ch < NCH; ++ch) {
        if (ch + 1 < NCH)
            asm volatile("cp.async.wait_group 1;" ::: "memory");
        else
            asm volatile("cp.async.wait_group 0;" ::: "memory");
        __syncthreads();

        const int stage = ch % 3;
        const uint32_t Ab = smb + stage * STAGE_B;
        const uint32_t Bb = Ab + 2 * TILE_B;
#pragma unroll
        for (int kk = 0; kk < 2; ++kk) {
            const int kc = kk * 16;
            uint32_t ah[2][4], al[2][4], bh[2][4], bl[2][4];
#pragma unroll
            for (int mi = 0; mi < 2; ++mi) {
                const int r = warp_m + mi * 16 + (lane & 7) + ((lane >> 3) & 1) * 8;
                const int c = kc + (lane >> 4) * 8;
                const uint32_t ad = Ab + r * PITCH + c * 2;
                ldm4(ah[mi], ad);
                ldm4(al[mi], ad + TILE_B);
            }
#pragma unroll
            for (int gi = 0; gi < 2; ++gi) {
                const int r = warp_n + gi * 16 + ((lane >> 4) & 1) * 8 + (lane & 7);
                const int c = kc + ((lane >> 3) & 1) * 8;
                const uint32_t bd = Bb + r * PITCH + c * 2;
                ldm4(bh[gi], bd);
                ldm4(bl[gi], bd + TILE_B);
            }
#pragma unroll
            for (int mi = 0; mi < 2; ++mi)
#pragma unroll
                for (int ni = 0; ni < 4; ++ni) {
                    const uint32_t* bhp = &bh[ni >> 1][(ni & 1) * 2];
                    const uint32_t* blp = &bl[ni >> 1][(ni & 1) * 2];
                    mma16816(acc[mi][ni], ah[mi], bhp);
                    mma16816(acc[mi][ni], ah[mi], blp);
                    mma16816(acc[mi][ni], al[mi], bhp);
                }
        }
        // write target stage (ch+2)%3 was last read at chunk ch-1; the barrier
        // at the top of this chunk proves all warps finished it -> WAR-safe.
        if (ch + 2 < NCH)
            load_chunk((ch + 2) % 3, ch + 2);
    }

    // ---------------- epilogue ----------------
#pragma unroll
    for (int mi = 0; mi < 2; ++mi)
#pragma unroll
        for (int ni = 0; ni < 4; ++ni)
#pragma unroll
            for (int half = 0; half < 2; ++half) {
                const int gm = row0 + warp_m + mi * 16 + (lane >> 2) + half * 8;
                const int gn = n0 + warp_n + ni * 8 + 2 * (lane & 3);
                float v0 = acc[mi][ni][half * 2 + 0];
                float v1 = acc[mi][ni][half * 2 + 1];
                if (MODE == 1) {
                    const int kk = gm >> 7, g = gm & 127;
                    const int b = gn >> 10, m = gn & 1023;
                    __nv_bfloat16 h0, l0, h1, l1;
                    split2(v0, h0, l0); split2(v1, h1, l1);
                    const size_t o = ((size_t)(b * 128 + g)) * 4096 + kk * 1024 + m;
                    *(__nv_bfloat162*)(g_Sth + o) = __halves2bfloat162(h0, h1);
                    *(__nv_bfloat162*)(g_Stl + o) = __halves2bfloat162(l0, l1);
                } else {
                    *(float2*)(g_Cpart + (size_t)blockIdx.z * 1048576u
                                       + (size_t)gm * 1024 + gn)
                        = make_float2(v0, v1);
                }
            }
}

// ---------------- reduce kernels ----------------
__global__ void reduce_pow_k(int slot)
{
    const size_t e = ((size_t)blockIdx.x * 256 + threadIdx.x) * 4;
    const float4 a = *(const float4*)(g_Cpart + e);
    const float4 b = *(const float4*)(g_Cpart + 1048576u + e);
    const float4 c = *(const float4*)(g_Cpart + 2097152u + e);
    const float4 d = *(const float4*)(g_Cpart + 3145728u + e);
    const float4 s = make_float4(a.x + b.x + c.x + d.x, a.y + b.y + c.y + d.y,
                                 a.z + b.z + c.z + d.z, a.w + b.w + c.w + d.w);
    const int m = (int)(e >> 10), n = (int)(e & 1023);
    __nv_bfloat16 h0, l0, h1, l1, h2, l2, h3, l3;
    split2(s.x, h0, l0); split2(s.y, h1, l1);
    split2(s.z, h2, l2); split2(s.w, h3, l3);
    const size_t o = (size_t)m * 4096 + (size_t)slot * 1024 + n;
    *(__nv_bfloat162*)(g_Lh + o)     = __halves2bfloat162(h0, h1);
    *(__nv_bfloat162*)(g_Lh + o + 2) = __halves2bfloat162(h2, h3);
    *(__nv_bfloat162*)(g_Ll + o)     = __halves2bfloat162(l0, l1);
    *(__nv_bfloat162*)(g_Ll + o + 2) = __halves2bfloat162(l2, l3);
}

__global__ void reduce_relu_k(float* __restrict__ out, int t)
{
    const size_t e = ((size_t)blockIdx.x * 256 + threadIdx.x) * 4;
    float4 s = *(const float4*)(g_Cpart + e);
#pragma unroll
    for (int z = 1; z < 8; ++z) {
        const float4 p = *(const float4*)(g_Cpart + (size_t)z * 1048576u + e);
        s.x += p.x; s.y += p.y; s.z += p.z; s.w += p.w;
    }
    s.x = fmaxf(s.x, 0.f); s.y = fmaxf(s.y, 0.f);
    s.z = fmaxf(s.z, 0.f); s.w = fmaxf(s.w, 0.f);
    const int m = (int)(e >> 10);
    const int j = (int)(e & 1023);
    const int b8 = j >> 7, g = j & 127;
    *(float4*)(out + (((size_t)(b8 * 16 + t)) * 1024 + m) * 128 + g) = s;
    __nv_bfloat16 h0, l0, h1, l1, h2, l2, h3, l3;
    split2(s.x, h0, l0); split2(s.y, h1, l1);
    split2(s.z, h2, l2); split2(s.w, h3, l3);
    const size_t ho = ((size_t)(b8 * 1024 + m)) * 128 + g;
    *(__nv_bfloat162*)(g_hh + ho)     = __halves2bfloat162(h0, h1);
    *(__nv_bfloat162*)(g_hh + ho + 2) = __halves2bfloat162(h2, h3);
    *(__nv_bfloat162*)(g_hl + ho)     = __halves2bfloat162(l0, l1);
    *(__nv_bfloat162*)(g_hl + ho + 2) = __halves2bfloat162(l2, l3);
}

// ---------------- prep kernels ----------------
__global__ void splitL0_k(const float* __restrict__ L)
{
    const int e = blockIdx.x * 256 + threadIdx.x;       // 1M
    const int r = e >> 10, c = e & 1023;
    __nv_bfloat16 h, l;
    split2(L[e], h, l);
    g_Lh[(size_t)r * 4096 + c] = h;
    g_Ll[(size_t)r * 4096 + c] = l;
}

__global__ void transLT_k(const float* __restrict__ L)
{
    __shared__ float tile[32][33];
    const int bx = blockIdx.x * 32, by = blockIdx.y * 32;
    const int x = threadIdx.x, y = threadIdx.y;          // block (32, 8)
#pragma unroll
    for (int i = 0; i < 32; i += 8)
        tile[y + i][x] = L[(size_t)(by + y + i) * 1024 + bx + x];
    __syncthreads();
#pragma unroll
    for (int i = 0; i < 32; i += 8) {
        __nv_bfloat16 h, l;
        split2(tile[x][y + i], h, l);                    // = L[by+x][bx+y+i]
        const size_t o = (size_t)(bx + y + i) * 1024 + by + x;
        g_LTh[o] = h;
        g_LTl[o] = l;
    }
}

__global__ void splitX_k(const float* __restrict__ x)
{
    const size_t e = ((size_t)blockIdx.x * 256 + threadIdx.x) * 4;
    const float4 v = *(const float4*)(x + e);
    __nv_bfloat16 h0, l0, h1, l1, h2, l2, h3, l3;
    split2(v.x, h0, l0); split2(v.y, h1, l1);
    split2(v.z, h2, l2); split2(v.w, h3, l3);
    *(__nv_bfloat162*)(g_xh + e)     = __halves2bfloat162(h0, h1);
    *(__nv_bfloat162*)(g_xh + e + 2) = __halves2bfloat162(h2, h3);
    *(__nv_bfloat162*)(g_xl + e)     = __halves2bfloat162(l0, l1);
    *(__nv_bfloat162*)(g_xl + e + 2) = __halves2bfloat162(l2, l3);
}

__global__ void catWHT_k(const float* __restrict__ W, const float* __restrict__ H)
{
    const int e = blockIdx.x * 256 + threadIdx.x;        // 512*256
    const int kg = e >> 8, f = e & 255;
    const int k = kg >> 7, g = kg & 127;
    const float v = (f < 128) ? W[k * 16384 + f * 128 + g]
                              : H[k * 16384 + (f - 128) * 128 + g];
    __nv_bfloat16 hi, lo;
    split2(v, hi, lo);
    g_WHTh[e] = hi;
    g_WHTl[e] = lo;
}

__global__ void zeroH_k()
{
    const size_t e = ((size_t)blockIdx.x * 256 + threadIdx.x) * 4;
    *(uint2*)(g_hh + e) = make_uint2(0u, 0u);
    *(uint2*)(g_hl + e) = make_uint2(0u, 0u);
}

// ---------------- launch ----------------
extern "C" void kernel_launch(void* const* d_in, const int* in_sizes, int n_in,
                              void* d_out, int out_size)
{
    const float* x = (const float*)d_in[0]; // [8,16,1024,128]
    const float* L = (const float*)d_in[1]; // [1024,1024]
    const float* W = (const float*)d_in[2]; // [4,128,128]
    const float* H = (const float*)d_in[3]; // [4,128,128]
    float* out = (float*)d_out;
    (void)in_sizes; (void)n_in; (void)out_size;

    cudaFuncSetAttribute(mma_k<0>, cudaFuncAttributeMaxDynamicSharedMemorySize, SMEM_TOT);
    cudaFuncSetAttribute(mma_k<1>, cudaFuncAttributeMaxDynamicSharedMemorySize, SMEM_TOT);
    cudaFuncSetAttribute(mma_k<2>, cudaFuncAttributeMaxDynamicSharedMemorySize, SMEM_TOT);

    splitL0_k<<<4096, 256>>>(L);                           // 0
    transLT_k<<<dim3(32, 32), dim3(32, 8)>>>(L);           // 1
    catWHT_k <<<512, 256>>>(W, H);                         // 2
    zeroH_k  <<<1024, 256>>>();                            // 3
    splitX_k <<<16384, 256>>>(x);                          // 4

    // L powers: split-K=4 + reduce/split
    for (int s = 1; s < 4; ++s) {                          // 5..10
        mma_k<2><<<dim3(16, 16, 4), 128, SMEM_TOT>>>(nullptr, s);
        reduce_pow_k<<<1024, 256>>>(s);
    }

    for (int t = 0; t < 16; ++t) {
        mma_k<1><<<dim3(128, 8), 128, SMEM_TOT>>>(nullptr, t);       // St
        mma_k<0><<<dim3(16, 16, 8), 128, SMEM_TOT>>>(nullptr, t);    // Cpart
        reduce_relu_k<<<1024, 256>>>(out, t);                        // out, h
    }
}

// round 12
// speedup vs baseline: 1.5317x; 1.2471x over previous
#include <cuda_runtime.h>
#include <cuda_bf16.h>
#include <cstdint>

// ============================================================================
// RGNN via warp-level mma.sync, bf16x3 split precision (sm_100-safe path).
//   h_t = relu( sum_k L^{k+1} (x_t W_k + h_{t-1} H_k) ), B=8,T=16,N=1024,F=128,K=4
//
// R11: 128x128 CTA tile (halves L2 smem-fill traffic, which was co-limiting),
// XOR-swizzled 64B-pitch smem (stage 32KB, 3-stage ring = 96KB -> 2 CTAs/SM,
// 16 warps), warp tile 32x64, MMA:LDSM = 4:1.
//
//   MODE 2 (powers):  Cpart[z] = Lslot[s-1] @ L^T (K=256/z,z<4) -> reduce/split
//   MODE 1 (feature): St[(k,g)][(b,m)] = WHT @ [x_t|h]  K=256, grid 64x4
//   MODE 0 (main):    Cpart[z] = Lcat @ St^T (K=512/z,z<8) -> reduce/relu
// ============================================================================

// ---------------- device globals ----------------
__device__ __align__(256) __nv_bfloat16 g_Lh  [1024u * 4096u]; // L^1..L^4 hi [m][k]
__device__ __align__(256) __nv_bfloat16 g_Ll  [1024u * 4096u]; // lo
__device__ __align__(256) __nv_bfloat16 g_LTh [1024u * 1024u]; // L^T hi [n][k]
__device__ __align__(256) __nv_bfloat16 g_LTl [1024u * 1024u];
__device__ __align__(256) __nv_bfloat16 g_Sth [1024u * 4096u]; // St hi [(b,g)][(k,m)]
__device__ __align__(256) __nv_bfloat16 g_Stl [1024u * 4096u];
__device__ __align__(256) __nv_bfloat16 g_xh  [16777216u];     // x hi [b][t][n][f]
__device__ __align__(256) __nv_bfloat16 g_xl  [16777216u];
__device__ __align__(256) __nv_bfloat16 g_hh  [1048576u];      // h hi [(b*1024+n)][f]
__device__ __align__(256) __nv_bfloat16 g_hl  [1048576u];
__device__ __align__(256) __nv_bfloat16 g_WHTh[512u * 256u];   // WHT hi [(k*128+g)][f']
__device__ __align__(256) __nv_bfloat16 g_WHTl[512u * 256u];
__device__ __align__(256) float         g_Cpart[8u * 1024u * 1024u]; // split-K partials

// ---------------- helpers ----------------
__device__ __forceinline__ uint32_t smem_u32(const void* p) {
    uint32_t a;
    asm("{ .reg .u64 t; cvta.to.shared.u64 t, %1; cvt.u32.u64 %0, t; }"
        : "=r"(a) : "l"(p));
    return a;
}
__device__ __forceinline__ void cp16(uint32_t dst, const void* src) {
    asm volatile("cp.async.cg.shared.global [%0], [%1], 16;" :: "r"(dst), "l"(src));
}
__device__ __forceinline__ void ldm4(uint32_t* r, uint32_t a) {
    asm volatile("ldmatrix.sync.aligned.m8n8.x4.shared.b16 {%0,%1,%2,%3}, [%4];"
        : "=r"(r[0]), "=r"(r[1]), "=r"(r[2]), "=r"(r[3]) : "r"(a));
}
__device__ __forceinline__ void mma16816(float* d, const uint32_t* a, const uint32_t* b) {
    asm volatile(
        "mma.sync.aligned.m16n8k16.row.col.f32.bf16.bf16.f32 "
        "{%0,%1,%2,%3}, {%4,%5,%6,%7}, {%8,%9}, {%0,%1,%2,%3};"
        : "+f"(d[0]), "+f"(d[1]), "+f"(d[2]), "+f"(d[3])
        : "r"(a[0]), "r"(a[1]), "r"(a[2]), "r"(a[3]), "r"(b[0]), "r"(b[1]));
}
__device__ __forceinline__ void split2(float v, __nv_bfloat16& h, __nv_bfloat16& l) {
    h = __float2bfloat16(v);
    l = __float2bfloat16(v - __bfloat162float(h));
}

// ---------------- smem geometry ----------------
// 128 rows x 32 bf16 = 64B rows, XOR swizzle: quad ^= (r>>1)&3.
// cp.async phase (8 lanes) writes rows 2r..2r+1 = 128B across all banks once.
// ldmatrix phase (8 lanes) reads 8 consecutive rows; even rows' 4 quads and
// odd rows' 4 quads each get distinct slots -> conflict-free.
static constexpr int TILE_B   = 128 * 64;         // 8192
static constexpr int STAGE_B  = 4 * TILE_B;       // Ah, Al, Bh, Bl = 32768
static constexpr int STAGES   = 3;
static constexpr int SMEM_TOT = STAGES * STAGE_B; // 98304 -> 2 CTAs/SM

__device__ __forceinline__ uint32_t swz(int r, int quad) {
    return (uint32_t)(r * 64 + ((quad ^ ((r >> 1) & 3)) << 4));
}

// ============================================================================
// Unified GEMM kernel. CTA tile 128(m) x 128(n), 8 warps (4m x 2n, 32x64 each),
// k-chunk 32. 3-stage cp.async ring, prefetch distance 2.
// MODE 0: main  split-K=8 (K=512/CTA)  -> Cpart
// MODE 1: feature (K=256)              -> St splits
// MODE 2: powers split-K=4 (K=256/CTA) -> Cpart
// ============================================================================
template<int MODE>
__global__ __launch_bounds__(256, 2)
void mma_k(float* __restrict__ out, const int targ)   // targ = t (0,1) or slot (2)
{
    extern __shared__ __align__(128) char sm[];
    const uint32_t smb = smem_u32(sm);
    const int tid  = threadIdx.x;
    const int wid  = tid >> 5, lane = tid & 31;
    const int row0 = blockIdx.y * 128;
    const int n0   = blockIdx.x * 128;

    constexpr int NCH = (MODE == 0) ? 16 : 8;     // k-chunks of 32 per CTA
    const int kbase = (MODE == 1) ? 0 : blockIdx.z * (NCH * 32);

    const __nv_bfloat16 *Ah, *Al;
    int lda;
    if (MODE == 1) {
        Ah = g_WHTh + (size_t)row0 * 256; Al = g_WHTl + (size_t)row0 * 256; lda = 256;
    } else {
        const int kofs = (MODE == 2) ? (targ - 1) * 1024 : 0;
        Ah = g_Lh + (size_t)row0 * 4096 + kofs;
        Al = g_Ll + (size_t)row0 * 4096 + kofs;
        lda = 4096;
    }

    auto load_chunk = [&](int stage, int ch) {
        const int k0 = kbase + ch * 32;
        const uint32_t base = smb + stage * STAGE_B;
        // A: 128 rows x 32 bf16, hi+lo
#pragma unroll
        for (int i = 0; i < 2; ++i) {
            const int idx = i * 256 + tid;          // 0..511
            const int r = idx >> 2, c16 = idx & 3;
            const size_t o = (size_t)r * lda + k0 + c16 * 8;
            const uint32_t d = base + swz(r, c16);
            cp16(d,          Ah + o);
            cp16(d + TILE_B, Al + o);
        }
        // B: 128 rows x 32 bf16, hi+lo
#pragma unroll
        for (int i = 0; i < 2; ++i) {
            const int idx = i * 256 + tid;
            const int r = idx >> 2, c16 = idx & 3;
            const __nv_bfloat16 *sh, *sl;
            if (MODE == 0) {
                const size_t o = (size_t)(n0 + r) * 4096 + k0 + c16 * 8;
                sh = g_Sth + o; sl = g_Stl + o;
            } else if (MODE == 2) {
                const size_t o = (size_t)(n0 + r) * 1024 + k0 + c16 * 8;
                sh = g_LTh + o; sl = g_LTl + o;
            } else {
                const int j = n0 + r, b = j >> 10, m = j & 1023;
                if (k0 < 128) {
                    const size_t o = (((size_t)(b * 16 + targ)) * 1024 + m) * 128
                                   + k0 + c16 * 8;
                    sh = g_xh + o; sl = g_xl + o;
                } else {
                    const size_t o = ((size_t)(b * 1024 + m)) * 128
                                   + (k0 - 128) + c16 * 8;
                    sh = g_hh + o; sl = g_hl + o;
                }
            }
            const uint32_t d = base + 2 * TILE_B + swz(r, c16);
            cp16(d,          sh);
            cp16(d + TILE_B, sl);
        }
        asm volatile("cp.async.commit_group;" ::: "memory");
    };

    const int warp_m = (wid & 3) * 32;     // 4 warps along m
    const int warp_n = (wid >> 2) * 64;    // 2 warps along n (64 cols each)

    float acc[2][8][4];
#pragma unroll
    for (int a = 0; a < 2; ++a)
#pragma unroll
        for (int b = 0; b < 8; ++b)
#pragma unroll
            for (int c = 0; c < 4; ++c) acc[a][b][c] = 0.f;

    // prefetch 2 chunks (NCH >= 8 in all modes)
    load_chunk(0, 0);
    load_chunk(1, 1);

#pragma unroll 1
    for (int ch = 0; ch < NCH; ++ch) {
        if (ch + 1 < NCH)
            asm volatile("cp.async.wait_group 1;" ::: "memory");
        else
            asm volatile("cp.async.wait_group 0;" ::: "memory");
        __syncthreads();

        const int stage = ch % 3;
        const uint32_t Ab = smb + stage * STAGE_B;
        const uint32_t Bb = Ab + 2 * TILE_B;
#pragma unroll
        for (int kk = 0; kk < 2; ++kk) {
            const int kc = kk * 16;
            uint32_t ah[2][4], al[2][4];
#pragma unroll
            for (int mi = 0; mi < 2; ++mi) {
                const int r = warp_m + mi * 16 + (lane & 7) + ((lane >> 3) & 1) * 8;
                const int c = kc + (lane >> 4) * 8;
                const uint32_t ad = Ab + swz(r, c >> 3);
                ldm4(ah[mi], ad);
                ldm4(al[mi], ad + TILE_B);
            }
            // process n in 32-col halves to bound live registers
#pragma unroll
            for (int nh = 0; nh < 2; ++nh) {
                uint32_t bh[2][4], bl[2][4];
#pragma unroll
                for (int gj = 0; gj < 2; ++gj) {
                    const int gi = nh * 2 + gj;
                    const int r = warp_n + gi * 16 + ((lane >> 4) & 1) * 8 + (lane & 7);
                    const int c = kc + ((lane >> 3) & 1) * 8;
                    const uint32_t bd = Bb + swz(r, c >> 3);
                    ldm4(bh[gj], bd);
                    ldm4(bl[gj], bd + TILE_B);
                }
#pragma unroll
                for (int mi = 0; mi < 2; ++mi)
#pragma unroll
                    for (int nj = 0; nj < 4; ++nj) {
                        const int ni = nh * 4 + nj;
                        const uint32_t* bhp = &bh[nj >> 1][(nj & 1) * 2];
                        const uint32_t* blp = &bl[nj >> 1][(nj & 1) * 2];
                        mma16816(acc[mi][ni], ah[mi], bhp);
                        mma16816(acc[mi][ni], ah[mi], blp);
                        mma16816(acc[mi][ni], al[mi], bhp);
                    }
            }
        }
        // write target stage (ch+2)%3 was last read at chunk ch-1; the barrier
        // at the top of this chunk proves all warps finished it -> WAR-safe.
        if (ch + 2 < NCH)
            load_chunk((ch + 2) % 3, ch + 2);
    }

    // ---------------- epilogue ----------------
#pragma unroll
    for (int mi = 0; mi < 2; ++mi)
#pragma unroll
        for (int ni = 0; ni < 8; ++ni)
#pragma unroll
            for (int half = 0; half < 2; ++half) {
                const int gm = row0 + warp_m + mi * 16 + (lane >> 2) + half * 8;
                const int gn = n0 + warp_n + ni * 8 + 2 * (lane & 3);
                float v0 = acc[mi][ni][half * 2 + 0];
                float v1 = acc[mi][ni][half * 2 + 1];
                if (MODE == 1) {
                    const int kk = gm >> 7, g = gm & 127;
                    const int b = gn >> 10, m = gn & 1023;
                    __nv_bfloat16 h0, l0, h1, l1;
                    split2(v0, h0, l0); split2(v1, h1, l1);
                    const size_t o = ((size_t)(b * 128 + g)) * 4096 + kk * 1024 + m;
                    *(__nv_bfloat162*)(g_Sth + o) = __halves2bfloat162(h0, h1);
                    *(__nv_bfloat162*)(g_Stl + o) = __halves2bfloat162(l0, l1);
                } else {
                    *(float2*)(g_Cpart + (size_t)blockIdx.z * 1048576u
                                       + (size_t)gm * 1024 + gn)
                        = make_float2(v0, v1);
                }
            }
}

// ---------------- reduce kernels ----------------
__global__ void reduce_pow_k(int slot)
{
    const size_t e = ((size_t)blockIdx.x * 256 + threadIdx.x) * 4;
    const float4 a = *(const float4*)(g_Cpart + e);
    const float4 b = *(const float4*)(g_Cpart + 1048576u + e);
    const float4 c = *(const float4*)(g_Cpart + 2097152u + e);
    const float4 d = *(const float4*)(g_Cpart + 3145728u + e);
    const float4 s = make_float4(a.x + b.x + c.x + d.x, a.y + b.y + c.y + d.y,
                                 a.z + b.z + c.z + d.z, a.w + b.w + c.w + d.w);
    const int m = (int)(e >> 10), n = (int)(e & 1023);
    __nv_bfloat16 h0, l0, h1, l1, h2, l2, h3, l3;
    split2(s.x, h0, l0); split2(s.y, h1, l1);
    split2(s.z, h2, l2); split2(s.w, h3, l3);
    const size_t o = (size_t)m * 4096 + (size_t)slot * 1024 + n;
    *(__nv_bfloat162*)(g_Lh + o)     = __halves2bfloat162(h0, h1);
    *(__nv_bfloat162*)(g_Lh + o + 2) = __halves2bfloat162(h2, h3);
    *(__nv_bfloat162*)(g_Ll + o)     = __halves2bfloat162(l0, l1);
    *(__nv_bfloat162*)(g_Ll + o + 2) = __halves2bfloat162(l2, l3);
}

__global__ void reduce_relu_k(float* __restrict__ out, int t)
{
    const size_t e = ((size_t)blockIdx.x * 256 + threadIdx.x) * 4;
    float4 s = *(const float4*)(g_Cpart + e);
#pragma unroll
    for (int z = 1; z < 8; ++z) {
        const float4 p = *(const float4*)(g_Cpart + (size_t)z * 1048576u + e);
        s.x += p.x; s.y += p.y; s.z += p.z; s.w += p.w;
    }
    s.x = fmaxf(s.x, 0.f); s.y = fmaxf(s.y, 0.f);
    s.z = fmaxf(s.z, 0.f); s.w = fmaxf(s.w, 0.f);
    const int m = (int)(e >> 10);
    const int j = (int)(e & 1023);
    const int b8 = j >> 7, g = j & 127;
    *(float4*)(out + (((size_t)(b8 * 16 + t)) * 1024 + m) * 128 + g) = s;
    __nv_bfloat16 h0, l0, h1, l1, h2, l2, h3, l3;
    split2(s.x, h0, l0); split2(s.y, h1, l1);
    split2(s.z, h2, l2); split2(s.w, h3, l3);
    const size_t ho = ((size_t)(b8 * 1024 + m)) * 128 + g;
    *(__nv_bfloat162*)(g_hh + ho)     = __halves2bfloat162(h0, h1);
    *(__nv_bfloat162*)(g_hh + ho + 2) = __halves2bfloat162(h2, h3);
    *(__nv_bfloat162*)(g_hl + ho)     = __halves2bfloat162(l0, l1);
    *(__nv_bfloat162*)(g_hl + ho + 2) = __halves2bfloat162(l2, l3);
}

// ---------------- prep kernels ----------------
__global__ void splitL0_k(const float* __restrict__ L)
{
    const int e = blockIdx.x * 256 + threadIdx.x;       // 1M
    const int r = e >> 10, c = e & 1023;
    __nv_bfloat16 h, l;
    split2(L[e], h, l);
    g_Lh[(size_t)r * 4096 + c] = h;
    g_Ll[(size_t)r * 4096 + c] = l;
}

__global__ void transLT_k(const float* __restrict__ L)
{
    __shared__ float tile[32][33];
    const int bx = blockIdx.x * 32, by = blockIdx.y * 32;
    const int x = threadIdx.x, y = threadIdx.y;          // block (32, 8)
#pragma unroll
    for (int i = 0; i < 32; i += 8)
        tile[y + i][x] = L[(size_t)(by + y + i) * 1024 + bx + x];
    __syncthreads();
#pragma unroll
    for (int i = 0; i < 32; i += 8) {
        __nv_bfloat16 h, l;
        split2(tile[x][y + i], h, l);                    // = L[by+x][bx+y+i]
        const size_t o = (size_t)(bx + y + i) * 1024 + by + x;
        g_LTh[o] = h;
        g_LTl[o] = l;
    }
}

__global__ void splitX_k(const float* __restrict__ x)
{
    const size_t e = ((size_t)blockIdx.x * 256 + threadIdx.x) * 4;
    const float4 v = *(const float4*)(x + e);
    __nv_bfloat16 h0, l0, h1, l1, h2, l2, h3, l3;
    split2(v.x, h0, l0); split2(v.y, h1, l1);
    split2(v.z, h2, l2); split2(v.w, h3, l3);
    *(__nv_bfloat162*)(g_xh + e)     = __halves2bfloat162(h0, h1);
    *(__nv_bfloat162*)(g_xh + e + 2) = __halves2bfloat162(h2, h3);
    *(__nv_bfloat162*)(g_xl + e)     = __halves2bfloat162(l0, l1);
    *(__nv_bfloat162*)(g_xl + e + 2) = __halves2bfloat162(l2, l3);
}

__global__ void catWHT_k(const float* __restrict__ W, const float* __restrict__ H)
{
    const int e = blockIdx.x * 256 + threadIdx.x;        // 512*256
    const int kg = e >> 8, f = e & 255;
    const int k = kg >> 7, g = kg & 127;
    const float v = (f < 128) ? W[k * 16384 + f * 128 + g]
                              : H[k * 16384 + (f - 128) * 128 + g];
    __nv_bfloat16 hi, lo;
    split2(v, hi, lo);
    g_WHTh[e] = hi;
    g_WHTl[e] = lo;
}

__global__ void zeroH_k()
{
    const size_t e = ((size_t)blockIdx.x * 256 + threadIdx.x) * 4;
    *(uint2*)(g_hh + e) = make_uint2(0u, 0u);
    *(uint2*)(g_hl + e) = make_uint2(0u, 0u);
}

// ---------------- launch ----------------
extern "C" void kernel_launch(void* const* d_in, const int* in_sizes, int n_in,
                              void* d_out, int out_size)
{
    const float* x = (const float*)d_in[0]; // [8,16,1024,128]
    const float* L = (const float*)d_in[1]; // [1024,1024]
    const float* W = (const float*)d_in[2]; // [4,128,128]
    const float* H = (const float*)d_in[3]; // [4,128,128]
    float* out = (float*)d_out;
    (void)in_sizes; (void)n_in; (void)out_size;

    cudaFuncSetAttribute(mma_k<0>, cudaFuncAttributeMaxDynamicSharedMemorySize, SMEM_TOT);
    cudaFuncSetAttribute(mma_k<1>, cudaFuncAttributeMaxDynamicSharedMemorySize, SMEM_TOT);
    cudaFuncSetAttribute(mma_k<2>, cudaFuncAttributeMaxDynamicSharedMemorySize, SMEM_TOT);

    splitL0_k<<<4096, 256>>>(L);                           // 0
    transLT_k<<<dim3(32, 32), dim3(32, 8)>>>(L);           // 1
    catWHT_k <<<512, 256>>>(W, H);                         // 2
    zeroH_k  <<<1024, 256>>>();                            // 3
    splitX_k <<<16384, 256>>>(x);                          // 4

    // L powers: split-K=4 + reduce/split
    for (int s = 1; s < 4; ++s) {                          // 5..10
        mma_k<2><<<dim3(8, 8, 4), 256, SMEM_TOT>>>(nullptr, s);
        reduce_pow_k<<<1024, 256>>>(s);
    }

    for (int t = 0; t < 16; ++t) {
        mma_k<1><<<dim3(64, 4), 256, SMEM_TOT>>>(nullptr, t);       // St
        mma_k<0><<<dim3(8, 8, 8), 256, SMEM_TOT>>>(nullptr, t);     // Cpart
        reduce_relu_k<<<1024, 256>>>(out, t);                       // out, h
    }
}